// round 5
// baseline (speedup 1.0000x reference)
#include <cuda_runtime.h>

// ---------------------------------------------------------------------------
// ContractiveEquivariantMPlayer fused kernel (fp32, f32x2-packed SIMT GEMM)
//
// Pipeline per block (128 atoms, 512 threads):
//   stage0 : load d, mapping, unit_r; build rbf_T[64][128] in smem (k-major)
//   GEMM1  : T1 = ssp(rbf @ Wf1 + bf1)            -> SB (k-major, swizzled)
//   GEMM2  : edge = h * (T1 @ Wf2 + bf2)          -> SA (k-major, swizzled)
//   GEMM3a : fa = edge @ Wa + ba                  -> SB (row-major)
//   GEMM3b : fb = edge @ Wb + bb                  -> regs
//   scatter: red.global.add.v4 of fb into dh[bead], fa*ur+fb*v into dv[bead]
// then finalize kernel divides by per-bead counts (scatter mean).
// ---------------------------------------------------------------------------

#define THREADS 512
#define TM      128      // atoms per block
#define FDIM    128

// smem layout in float4 units
#define SA_OFF     0      // 128 * 33 = 4224 f4  (rbf_T, later edge_inv_T)
#define SB_OFF     4224   // 128 * 33 = 4224 f4  (T1_T, later fa row-major)
#define SW_OFF     8448   // 2 * 1024 = 2048 f4  (weight tile double buffer)
#define SMALL_OFF  10496  // 160 f4: sd[128] f, smap[128] i, sur[384] f
#define SMEM_F4    10656
#define SMEM_BYTES (SMEM_F4 * 16)

typedef unsigned long long ull;

__device__ unsigned int g_cnt[32768];   // per-bead atom counts (B <= 32768)

// ---------------- packed fp32x2 helpers ----------------
__device__ __forceinline__ ull pack2(float x) {
    ull r; asm("mov.b64 %0, {%1, %1};" : "=l"(r) : "f"(x)); return r;
}
__device__ __forceinline__ void fma2(ull& c, ull a, ull b) {
    asm("fma.rn.f32x2 %0, %1, %2, %0;" : "+l"(c) : "l"(a), "l"(b));
}
__device__ __forceinline__ void unpack2(ull a, float& x, float& y) {
    asm("mov.b64 {%0, %1}, %2;" : "=f"(x), "=f"(y) : "l"(a));
}
__device__ __forceinline__ void red4(float* p, float a, float b, float c, float d) {
    asm volatile("red.global.add.v4.f32 [%0], {%1,%2,%3,%4};"
                 :: "l"(p), "f"(a), "f"(b), "f"(c), "f"(d) : "memory");
}

__device__ __forceinline__ float ssp(float x) {
    // shifted softplus: softplus(x) - ln2, overflow-safe
    return fmaxf(x, 0.0f) + log1pf(expf(-fabsf(x))) - 0.69314718055994531f;
}

// ---------------- weight tile streaming ----------------
__device__ __forceinline__ void load_tile(float4 w[2], const float* __restrict__ Wg,
                                          int kt, int Kvalid, int tid) {
#pragma unroll
    for (int t = 0; t < 2; t++) {
        int idx = tid + t * THREADS;       // 0..1023
        int kk = idx >> 5, cf = idx & 31;  // tile row, float4 column
        int k = kt * 32 + kk;
        if (k < Kvalid) w[t] = *reinterpret_cast<const float4*>(Wg + k * FDIM + cf * 4);
        else            w[t] = make_float4(0.f, 0.f, 0.f, 0.f);
    }
}
__device__ __forceinline__ void store_tile(float4* buf, const float4 w[2], int tid) {
#pragma unroll
    for (int t = 0; t < 2; t++) buf[tid + t * THREADS] = w[t];
}

// ---------------- core GEMM: acc[16] (f32x2) = A_T @ W ----------------
// Thread computes rows r*4..r*4+3 x cols c*8..c*8+7.
// A_T layout: float4 at  k*33 + (rowgrp ^ ((k>>3)&7))
template <int KTILES>
__device__ __forceinline__ void run_gemm(const float4* __restrict__ A,
                                         const float* __restrict__ Wg, int Kvalid,
                                         float4* SW, int tid, int r, int c, ull acc[16]) {
#pragma unroll
    for (int i = 0; i < 16; i++) acc[i] = 0ULL;

    float4 wreg[2];
    load_tile(wreg, Wg, 0, Kvalid, tid);
    store_tile(SW, wreg, tid);
    __syncthreads();

#pragma unroll
    for (int kt = 0; kt < KTILES; kt++) {
        if (kt + 1 < KTILES) load_tile(wreg, Wg, kt + 1, Kvalid, tid);
        const float4* Wb = SW + (kt & 1) * 1024;
#pragma unroll 8
        for (int kk = 0; kk < 32; kk++) {
            int k = kt * 32 + kk;
            int sw = (k >> 3) & 7;
            float4 a = A[k * 33 + (r ^ sw)];
            ull ap0 = pack2(a.x), ap1 = pack2(a.y), ap2 = pack2(a.z), ap3 = pack2(a.w);
            const ulonglong2* wp = reinterpret_cast<const ulonglong2*>(Wb + kk * 32 + c * 2);
            ulonglong2 u0 = wp[0];
            ulonglong2 u1 = wp[1];
            fma2(acc[0],  ap0, u0.x); fma2(acc[1],  ap0, u0.y);
            fma2(acc[2],  ap0, u1.x); fma2(acc[3],  ap0, u1.y);
            fma2(acc[4],  ap1, u0.x); fma2(acc[5],  ap1, u0.y);
            fma2(acc[6],  ap1, u1.x); fma2(acc[7],  ap1, u1.y);
            fma2(acc[8],  ap2, u0.x); fma2(acc[9],  ap2, u0.y);
            fma2(acc[10], ap2, u1.x); fma2(acc[11], ap2, u1.y);
            fma2(acc[12], ap3, u0.x); fma2(acc[13], ap3, u0.y);
            fma2(acc[14], ap3, u1.x); fma2(acc[15], ap3, u1.y);
        }
        __syncthreads();
        if (kt + 1 < KTILES) {
            store_tile(SW + ((kt + 1) & 1) * 1024, wreg, tid);
            __syncthreads();
        }
    }
}

__device__ __forceinline__ void unpack_bias(const ull acc[16], const float* __restrict__ bias,
                                            int c, float val[4][8]) {
    float4 b0 = *reinterpret_cast<const float4*>(bias + c * 8);
    float4 b1 = *reinterpret_cast<const float4*>(bias + c * 8 + 4);
    float bb[8] = {b0.x, b0.y, b0.z, b0.w, b1.x, b1.y, b1.z, b1.w};
#pragma unroll
    for (int i = 0; i < 4; i++)
#pragma unroll
        for (int p = 0; p < 4; p++) {
            float x, y; unpack2(acc[i * 4 + p], x, y);
            val[i][2 * p]     = x + bb[2 * p];
            val[i][2 * p + 1] = y + bb[2 * p + 1];
        }
}

// transpose-write: val[row i][col j] -> A_T[k=col][rowgrp r] for next stage
__device__ __forceinline__ void write_AT(float4* Abuf, const float val[4][8], int r, int c) {
    int swc = c & 7;   // == ((c*8+j) >> 3) & 7 for j in 0..7
#pragma unroll
    for (int j = 0; j < 8; j++)
        Abuf[(c * 8 + j) * 33 + (r ^ swc)] = make_float4(val[0][j], val[1][j], val[2][j], val[3][j]);
}

// ---------------------------------------------------------------------------
__global__ void __launch_bounds__(THREADS, 1)
mp_kernel(const float* __restrict__ hg, const float* __restrict__ vg,
          const float* __restrict__ dg, const float* __restrict__ urg,
          const float* __restrict__ Wf1, const float* __restrict__ bf1,
          const float* __restrict__ Wf2, const float* __restrict__ bf2,
          const float* __restrict__ Wa,  const float* __restrict__ ba,
          const float* __restrict__ Wb,  const float* __restrict__ bb,
          const int* __restrict__ mapping, float* __restrict__ out,
          int N, int B) {
    extern __shared__ float4 smem4[];
    float4* SA = smem4 + SA_OFF;
    float4* SB = smem4 + SB_OFF;
    float4* SW = smem4 + SW_OFF;
    float*  sd   = (float*)(smem4 + SMALL_OFF);
    int*    smap = (int*)(sd + 128);
    float*  sur  = (float*)(smap + 128);

    const int tid = threadIdx.x;
    const int c = tid & 15;       // col group: cols c*8 .. c*8+7
    const int r = tid >> 4;       // row group: rows r*4 .. r*4+3
    const int base = blockIdx.x * TM;

    // ---- stage 0: per-atom scalars + counts ----
    if (tid < 128) {
        int atom = base + tid;
        float dv = 0.f; int mp = 0;
        if (atom < N) {
            dv = dg[atom];
            mp = mapping[atom];
            atomicAdd(&g_cnt[mp], 1u);
        }
        sd[tid] = dv; smap[tid] = mp;
    }
    if (tid < 384) {
        int gi = base * 3 + tid;
        sur[tid] = (gi < N * 3) ? urg[gi] : 0.f;
    }
    __syncthreads();

    // ---- rbf_T fill: [k=0..63][row=0..127], rows k>=50 zero-padded ----
    const float step  = 5.0f / 49.0f;                 // linspace(0,5,50) spacing
    const float coeff = -0.5f / (step * step);
    float* SAf = (float*)SA;
    for (int idx = tid; idx < 64 * 128; idx += THREADS) {
        int k = idx >> 7, row = idx & 127;
        float valf = 0.f;
        if (k < 50) {
            float diff = sd[row] - (float)k * step;
            valf = expf(coeff * diff * diff);
        }
        int f4i = k * 33 + ((row >> 2) ^ ((k >> 3) & 7));
        SAf[f4i * 4 + (row & 3)] = valf;
    }
    __syncthreads();

    ull acc[16];
    float val[4][8];

    // ---- GEMM1: T1 = ssp(rbf @ Wf1 + bf1) -> SB ----
    run_gemm<2>(SA, Wf1, 50, SW, tid, r, c, acc);
    unpack_bias(acc, bf1, c, val);
#pragma unroll
    for (int i = 0; i < 4; i++)
#pragma unroll
        for (int j = 0; j < 8; j++) val[i][j] = ssp(val[i][j]);
    write_AT(SB, val, r, c);
    __syncthreads();

    // ---- GEMM2: edge = h * (T1 @ Wf2 + bf2) -> SA ----
    run_gemm<4>(SB, Wf2, 128, SW, tid, r, c, acc);
    unpack_bias(acc, bf2, c, val);
#pragma unroll
    for (int i = 0; i < 4; i++) {
        int atom = base + r * 4 + i;
        float hh[8];
        if (atom < N) {
            float4 h0 = *reinterpret_cast<const float4*>(hg + (long)atom * FDIM + c * 8);
            float4 h1 = *reinterpret_cast<const float4*>(hg + (long)atom * FDIM + c * 8 + 4);
            hh[0]=h0.x; hh[1]=h0.y; hh[2]=h0.z; hh[3]=h0.w;
            hh[4]=h1.x; hh[5]=h1.y; hh[6]=h1.z; hh[7]=h1.w;
        } else {
#pragma unroll
            for (int j = 0; j < 8; j++) hh[j] = 0.f;
        }
#pragma unroll
        for (int j = 0; j < 8; j++) val[i][j] *= hh[j];
    }
    write_AT(SA, val, r, c);
    __syncthreads();

    // ---- GEMM3a: fa = edge @ Wa + ba -> SB (row-major, pitch 32 f4) ----
    run_gemm<4>(SA, Wa, 128, SW, tid, r, c, acc);
    unpack_bias(acc, ba, c, val);
#pragma unroll
    for (int i = 0; i < 4; i++) {
        int lr = r * 4 + i;
        SB[lr * 32 + c * 2]     = make_float4(val[i][0], val[i][1], val[i][2], val[i][3]);
        SB[lr * 32 + c * 2 + 1] = make_float4(val[i][4], val[i][5], val[i][6], val[i][7]);
    }
    __syncthreads();

    // ---- GEMM3b: fb = edge @ Wb + bb (kept in regs) ----
    run_gemm<4>(SA, Wb, 128, SW, tid, r, c, acc);
    unpack_bias(acc, bb, c, val);

    // ---- scatter: dh += fb ; dv += fa*ur + fb*v ----
    float* dhout = out;
    float* dvout = out + (long)B * FDIM;
#pragma unroll
    for (int i = 0; i < 4; i++) {
        int lr = r * 4 + i;
        int atom = base + lr;
        if (atom >= N) continue;
        int bead = smap[lr];
        float urx = sur[lr * 3 + 0], ury = sur[lr * 3 + 1], urz = sur[lr * 3 + 2];

        float* dhp = dhout + (long)bead * FDIM + c * 8;
        red4(dhp,     val[i][0], val[i][1], val[i][2], val[i][3]);
        red4(dhp + 4, val[i][4], val[i][5], val[i][6], val[i][7]);

        float4 fa0 = SB[lr * 32 + c * 2];
        float4 fa1 = SB[lr * 32 + c * 2 + 1];
        float fav[8] = {fa0.x, fa0.y, fa0.z, fa0.w, fa1.x, fa1.y, fa1.z, fa1.w};

        const float4* vp = reinterpret_cast<const float4*>(vg + (long)atom * 384 + c * 24);
        float vv[24];
#pragma unroll
        for (int t = 0; t < 6; t++) {
            float4 q = vp[t];
            vv[4*t] = q.x; vv[4*t+1] = q.y; vv[4*t+2] = q.z; vv[4*t+3] = q.w;
        }
        float dvv[24];
#pragma unroll
        for (int j = 0; j < 8; j++) {
            dvv[3*j]   = fav[j] * urx + val[i][j] * vv[3*j];
            dvv[3*j+1] = fav[j] * ury + val[i][j] * vv[3*j+1];
            dvv[3*j+2] = fav[j] * urz + val[i][j] * vv[3*j+2];
        }
        float* dvp = dvout + (long)bead * 384 + c * 24;
#pragma unroll
        for (int t = 0; t < 6; t++)
            red4(dvp + 4 * t, dvv[4*t], dvv[4*t+1], dvv[4*t+2], dvv[4*t+3]);
    }
}

// ---------------------------------------------------------------------------
__global__ void zero_kernel(float* __restrict__ out, int n, int B) {
    int i = blockIdx.x * blockDim.x + threadIdx.x;
    if (i < n) out[i] = 0.f;
    if (i < B) g_cnt[i] = 0u;
}

__global__ void finalize_kernel(float* __restrict__ out, int BF, int total) {
    int i = blockIdx.x * blockDim.x + threadIdx.x;
    if (i >= total) return;
    int b = (i < BF) ? (i >> 7) : ((i - BF) / 384);
    float cnt = (float)g_cnt[b];
    out[i] *= 1.0f / fmaxf(cnt, 1.0f);
}

// ---------------------------------------------------------------------------
extern "C" void kernel_launch(void* const* d_in, const int* in_sizes, int n_in,
                              void* d_out, int out_size) {
    const float* h   = (const float*)d_in[0];
    const float* vi  = (const float*)d_in[1];
    const float* d   = (const float*)d_in[2];
    const float* ur  = (const float*)d_in[3];
    const float* Wf1 = (const float*)d_in[4];
    const float* bf1 = (const float*)d_in[5];
    const float* Wf2 = (const float*)d_in[6];
    const float* bf2 = (const float*)d_in[7];
    // d_in[8..11] = W1,b1,W2,b2 : dead code in the reference forward
    const float* Wa  = (const float*)d_in[12];
    const float* ba  = (const float*)d_in[13];
    const float* Wb  = (const float*)d_in[14];
    const float* bb  = (const float*)d_in[15];
    const int* mapping = (const int*)d_in[16];
    float* out = (float*)d_out;

    int N = in_sizes[2];            // d_iI element count = atoms
    int B = out_size / 512;         // out = B*128 (dh) + B*384 (dv)

    cudaFuncSetAttribute(mp_kernel, cudaFuncAttributeMaxDynamicSharedMemorySize, SMEM_BYTES);

    zero_kernel<<<(out_size + 511) / 512, 512>>>(out, out_size, B);
    mp_kernel<<<(N + TM - 1) / TM, THREADS, SMEM_BYTES>>>(
        h, vi, d, ur, Wf1, bf1, Wf2, bf2, Wa, ba, Wb, bb, mapping, out, N, B);
    finalize_kernel<<<(out_size + 255) / 256, 256>>>(out, B * 128, out_size);
}

// round 6
// speedup vs baseline: 1.0011x; 1.0011x over previous
#include <cuda_runtime.h>

// ---------------------------------------------------------------------------
// ContractiveEquivariantMPlayer fused kernel (fp32, f32x2-packed SIMT GEMM)
//
// Pipeline per block (128 atoms, 512 threads):
//   stage0 : load d, mapping, unit_r; build rbf_T[64][128] in smem (k-major)
//   GEMM1  : T1 = ssp(rbf @ Wf1 + bf1)            -> SB (k-major, swizzled)
//   GEMM2  : edge = h * (T1 @ Wf2 + bf2)          -> SA (k-major, swizzled)
//   GEMM3a : fa = edge @ Wa + ba                  -> SB (row-major)
//   GEMM3b : fb = edge @ Wb + bb                  -> regs
//   scatter: red.global.add.v4 of fb into dh[bead], fa*ur+fb*v into dv[bead]
// then finalize kernel divides by per-bead counts (scatter mean).
// ---------------------------------------------------------------------------

#define THREADS 512
#define TM      128      // atoms per block
#define FDIM    128

// smem layout in float4 units
#define SA_OFF     0      // 128 * 33 = 4224 f4  (rbf_T, later edge_inv_T)
#define SB_OFF     4224   // 128 * 33 = 4224 f4  (T1_T, later fa row-major)
#define SW_OFF     8448   // 2 * 1024 = 2048 f4  (weight tile double buffer)
#define SMALL_OFF  10496  // 160 f4: sd[128] f, smap[128] i, sur[384] f
#define SMEM_F4    10656
#define SMEM_BYTES (SMEM_F4 * 16)

typedef unsigned long long ull;

__device__ unsigned int g_cnt[32768];   // per-bead atom counts (B <= 32768)

// ---------------- packed fp32x2 helpers ----------------
__device__ __forceinline__ ull pack2(float x) {
    ull r; asm("mov.b64 %0, {%1, %1};" : "=l"(r) : "f"(x)); return r;
}
__device__ __forceinline__ void fma2(ull& c, ull a, ull b) {
    asm("fma.rn.f32x2 %0, %1, %2, %0;" : "+l"(c) : "l"(a), "l"(b));
}
__device__ __forceinline__ void unpack2(ull a, float& x, float& y) {
    asm("mov.b64 {%0, %1}, %2;" : "=f"(x), "=f"(y) : "l"(a));
}
__device__ __forceinline__ void red4(float* p, float a, float b, float c, float d) {
    asm volatile("red.global.add.v4.f32 [%0], {%1,%2,%3,%4};"
                 :: "l"(p), "f"(a), "f"(b), "f"(c), "f"(d) : "memory");
}

__device__ __forceinline__ float ssp(float x) {
    // shifted softplus: softplus(x) - ln2, overflow-safe
    return fmaxf(x, 0.0f) + log1pf(expf(-fabsf(x))) - 0.69314718055994531f;
}

// ---------------- weight tile streaming ----------------
__device__ __forceinline__ void load_tile(float4 w[2], const float* __restrict__ Wg,
                                          int kt, int Kvalid, int tid) {
#pragma unroll
    for (int t = 0; t < 2; t++) {
        int idx = tid + t * THREADS;       // 0..1023
        int kk = idx >> 5, cf = idx & 31;  // tile row, float4 column
        int k = kt * 32 + kk;
        if (k < Kvalid) w[t] = *reinterpret_cast<const float4*>(Wg + k * FDIM + cf * 4);
        else            w[t] = make_float4(0.f, 0.f, 0.f, 0.f);
    }
}
__device__ __forceinline__ void store_tile(float4* buf, const float4 w[2], int tid) {
#pragma unroll
    for (int t = 0; t < 2; t++) buf[tid + t * THREADS] = w[t];
}

// ---------------- core GEMM: acc[16] (f32x2) = A_T @ W ----------------
// Thread computes rows r*4..r*4+3 x cols c*8..c*8+7.
// A_T layout: float4 at  k*33 + (rowgrp ^ ((k>>3)&7))
template <int KTILES>
__device__ __forceinline__ void run_gemm(const float4* __restrict__ A,
                                         const float* __restrict__ Wg, int Kvalid,
                                         float4* SW, int tid, int r, int c, ull acc[16]) {
#pragma unroll
    for (int i = 0; i < 16; i++) acc[i] = 0ULL;

    float4 wreg[2];
    load_tile(wreg, Wg, 0, Kvalid, tid);
    store_tile(SW, wreg, tid);
    __syncthreads();

#pragma unroll
    for (int kt = 0; kt < KTILES; kt++) {
        if (kt + 1 < KTILES) load_tile(wreg, Wg, kt + 1, Kvalid, tid);
        const float4* Wb = SW + (kt & 1) * 1024;
#pragma unroll 8
        for (int kk = 0; kk < 32; kk++) {
            int k = kt * 32 + kk;
            int sw = (k >> 3) & 7;
            float4 a = A[k * 33 + (r ^ sw)];
            ull ap0 = pack2(a.x), ap1 = pack2(a.y), ap2 = pack2(a.z), ap3 = pack2(a.w);
            const ulonglong2* wp = reinterpret_cast<const ulonglong2*>(Wb + kk * 32 + c * 2);
            ulonglong2 u0 = wp[0];
            ulonglong2 u1 = wp[1];
            fma2(acc[0],  ap0, u0.x); fma2(acc[1],  ap0, u0.y);
            fma2(acc[2],  ap0, u1.x); fma2(acc[3],  ap0, u1.y);
            fma2(acc[4],  ap1, u0.x); fma2(acc[5],  ap1, u0.y);
            fma2(acc[6],  ap1, u1.x); fma2(acc[7],  ap1, u1.y);
            fma2(acc[8],  ap2, u0.x); fma2(acc[9],  ap2, u0.y);
            fma2(acc[10], ap2, u1.x); fma2(acc[11], ap2, u1.y);
            fma2(acc[12], ap3, u0.x); fma2(acc[13], ap3, u0.y);
            fma2(acc[14], ap3, u1.x); fma2(acc[15], ap3, u1.y);
        }
        __syncthreads();
        if (kt + 1 < KTILES) {
            store_tile(SW + ((kt + 1) & 1) * 1024, wreg, tid);
            __syncthreads();
        }
    }
}

__device__ __forceinline__ void unpack_bias(const ull acc[16], const float* __restrict__ bias,
                                            int c, float val[4][8]) {
    float4 b0 = *reinterpret_cast<const float4*>(bias + c * 8);
    float4 b1 = *reinterpret_cast<const float4*>(bias + c * 8 + 4);
    float bb[8] = {b0.x, b0.y, b0.z, b0.w, b1.x, b1.y, b1.z, b1.w};
#pragma unroll
    for (int i = 0; i < 4; i++)
#pragma unroll
        for (int p = 0; p < 4; p++) {
            float x, y; unpack2(acc[i * 4 + p], x, y);
            val[i][2 * p]     = x + bb[2 * p];
            val[i][2 * p + 1] = y + bb[2 * p + 1];
        }
}

// transpose-write: val[row i][col j] -> A_T[k=col][rowgrp r] for next stage
__device__ __forceinline__ void write_AT(float4* Abuf, const float val[4][8], int r, int c) {
    int swc = c & 7;   // == ((c*8+j) >> 3) & 7 for j in 0..7
#pragma unroll
    for (int j = 0; j < 8; j++)
        Abuf[(c * 8 + j) * 33 + (r ^ swc)] = make_float4(val[0][j], val[1][j], val[2][j], val[3][j]);
}

// ---------------------------------------------------------------------------
__global__ void __launch_bounds__(THREADS, 1)
mp_kernel(const float* __restrict__ hg, const float* __restrict__ vg,
          const float* __restrict__ dg, const float* __restrict__ urg,
          const float* __restrict__ Wf1, const float* __restrict__ bf1,
          const float* __restrict__ Wf2, const float* __restrict__ bf2,
          const float* __restrict__ Wa,  const float* __restrict__ ba,
          const float* __restrict__ Wb,  const float* __restrict__ bb,
          const int* __restrict__ mapping, float* __restrict__ out,
          int N, int B) {
    extern __shared__ float4 smem4[];
    float4* SA = smem4 + SA_OFF;
    float4* SB = smem4 + SB_OFF;
    float4* SW = smem4 + SW_OFF;
    float*  sd   = (float*)(smem4 + SMALL_OFF);
    int*    smap = (int*)(sd + 128);
    float*  sur  = (float*)(smap + 128);

    const int tid = threadIdx.x;
    const int c = tid & 15;       // col group: cols c*8 .. c*8+7
    const int r = tid >> 4;       // row group: rows r*4 .. r*4+3
    const int base = blockIdx.x * TM;

    // ---- stage 0: per-atom scalars + counts ----
    if (tid < 128) {
        int atom = base + tid;
        float dv = 0.f; int mp = 0;
        if (atom < N) {
            dv = dg[atom];
            mp = mapping[atom];
            atomicAdd(&g_cnt[mp], 1u);
        }
        sd[tid] = dv; smap[tid] = mp;
    }
    if (tid < 384) {
        int gi = base * 3 + tid;
        sur[tid] = (gi < N * 3) ? urg[gi] : 0.f;
    }
    __syncthreads();

    // ---- rbf_T fill: [k=0..63][row=0..127], rows k>=50 zero-padded ----
    const float step  = 5.0f / 49.0f;                 // linspace(0,5,50) spacing
    const float coeff = -0.5f / (step * step);
    float* SAf = (float*)SA;
    for (int idx = tid; idx < 64 * 128; idx += THREADS) {
        int k = idx >> 7, row = idx & 127;
        float valf = 0.f;
        if (k < 50) {
            float diff = sd[row] - (float)k * step;
            valf = expf(coeff * diff * diff);
        }
        int f4i = k * 33 + ((row >> 2) ^ ((k >> 3) & 7));
        SAf[f4i * 4 + (row & 3)] = valf;
    }
    __syncthreads();

    ull acc[16];
    float val[4][8];

    // ---- GEMM1: T1 = ssp(rbf @ Wf1 + bf1) -> SB ----
    run_gemm<2>(SA, Wf1, 50, SW, tid, r, c, acc);
    unpack_bias(acc, bf1, c, val);
#pragma unroll
    for (int i = 0; i < 4; i++)
#pragma unroll
        for (int j = 0; j < 8; j++) val[i][j] = ssp(val[i][j]);
    write_AT(SB, val, r, c);
    __syncthreads();

    // ---- GEMM2: edge = h * (T1 @ Wf2 + bf2) -> SA ----
    run_gemm<4>(SB, Wf2, 128, SW, tid, r, c, acc);
    unpack_bias(acc, bf2, c, val);
#pragma unroll
    for (int i = 0; i < 4; i++) {
        int atom = base + r * 4 + i;
        float hh[8];
        if (atom < N) {
            float4 h0 = *reinterpret_cast<const float4*>(hg + (long)atom * FDIM + c * 8);
            float4 h1 = *reinterpret_cast<const float4*>(hg + (long)atom * FDIM + c * 8 + 4);
            hh[0]=h0.x; hh[1]=h0.y; hh[2]=h0.z; hh[3]=h0.w;
            hh[4]=h1.x; hh[5]=h1.y; hh[6]=h1.z; hh[7]=h1.w;
        } else {
#pragma unroll
            for (int j = 0; j < 8; j++) hh[j] = 0.f;
        }
#pragma unroll
        for (int j = 0; j < 8; j++) val[i][j] *= hh[j];
    }
    write_AT(SA, val, r, c);
    __syncthreads();

    // ---- GEMM3a: fa = edge @ Wa + ba -> SB (row-major, pitch 32 f4) ----
    run_gemm<4>(SA, Wa, 128, SW, tid, r, c, acc);
    unpack_bias(acc, ba, c, val);
#pragma unroll
    for (int i = 0; i < 4; i++) {
        int lr = r * 4 + i;
        SB[lr * 32 + c * 2]     = make_float4(val[i][0], val[i][1], val[i][2], val[i][3]);
        SB[lr * 32 + c * 2 + 1] = make_float4(val[i][4], val[i][5], val[i][6], val[i][7]);
    }
    __syncthreads();

    // ---- GEMM3b: fb = edge @ Wb + bb (kept in regs) ----
    run_gemm<4>(SA, Wb, 128, SW, tid, r, c, acc);
    unpack_bias(acc, bb, c, val);

    // ---- scatter: dh += fb ; dv += fa*ur + fb*v ----
    float* dhout = out;
    float* dvout = out + (long)B * FDIM;
#pragma unroll
    for (int i = 0; i < 4; i++) {
        int lr = r * 4 + i;
        int atom = base + lr;
        if (atom >= N) continue;
        int bead = smap[lr];
        float urx = sur[lr * 3 + 0], ury = sur[lr * 3 + 1], urz = sur[lr * 3 + 2];

        float* dhp = dhout + (long)bead * FDIM + c * 8;
        red4(dhp,     val[i][0], val[i][1], val[i][2], val[i][3]);
        red4(dhp + 4, val[i][4], val[i][5], val[i][6], val[i][7]);

        float4 fa0 = SB[lr * 32 + c * 2];
        float4 fa1 = SB[lr * 32 + c * 2 + 1];
        float fav[8] = {fa0.x, fa0.y, fa0.z, fa0.w, fa1.x, fa1.y, fa1.z, fa1.w};

        const float4* vp = reinterpret_cast<const float4*>(vg + (long)atom * 384 + c * 24);
        float vv[24];
#pragma unroll
        for (int t = 0; t < 6; t++) {
            float4 q = vp[t];
            vv[4*t] = q.x; vv[4*t+1] = q.y; vv[4*t+2] = q.z; vv[4*t+3] = q.w;
        }
        float dvv[24];
#pragma unroll
        for (int j = 0; j < 8; j++) {
            dvv[3*j]   = fav[j] * urx + val[i][j] * vv[3*j];
            dvv[3*j+1] = fav[j] * ury + val[i][j] * vv[3*j+1];
            dvv[3*j+2] = fav[j] * urz + val[i][j] * vv[3*j+2];
        }
        float* dvp = dvout + (long)bead * 384 + c * 24;
#pragma unroll
        for (int t = 0; t < 6; t++)
            red4(dvp + 4 * t, dvv[4*t], dvv[4*t+1], dvv[4*t+2], dvv[4*t+3]);
    }
}

// ---------------------------------------------------------------------------
__global__ void zero_kernel(float* __restrict__ out, int n, int B) {
    int i = blockIdx.x * blockDim.x + threadIdx.x;
    if (i < n) out[i] = 0.f;
    if (i < B) g_cnt[i] = 0u;
}

__global__ void finalize_kernel(float* __restrict__ out, int BF, int total) {
    int i = blockIdx.x * blockDim.x + threadIdx.x;
    if (i >= total) return;
    int b = (i < BF) ? (i >> 7) : ((i - BF) / 384);
    float cnt = (float)g_cnt[b];
    out[i] *= 1.0f / fmaxf(cnt, 1.0f);
}

// ---------------------------------------------------------------------------
extern "C" void kernel_launch(void* const* d_in, const int* in_sizes, int n_in,
                              void* d_out, int out_size) {
    const float* h   = (const float*)d_in[0];
    const float* vi  = (const float*)d_in[1];
    const float* d   = (const float*)d_in[2];
    const float* ur  = (const float*)d_in[3];
    const float* Wf1 = (const float*)d_in[4];
    const float* bf1 = (const float*)d_in[5];
    const float* Wf2 = (const float*)d_in[6];
    const float* bf2 = (const float*)d_in[7];
    // d_in[8..11] = W1,b1,W2,b2 : dead code in the reference forward
    const float* Wa  = (const float*)d_in[12];
    const float* ba  = (const float*)d_in[13];
    const float* Wb  = (const float*)d_in[14];
    const float* bb  = (const float*)d_in[15];
    const int* mapping = (const int*)d_in[16];
    float* out = (float*)d_out;

    int N = in_sizes[2];            // d_iI element count = atoms
    int B = out_size / 512;         // out = B*128 (dh) + B*384 (dv)

    cudaFuncSetAttribute(mp_kernel, cudaFuncAttributeMaxDynamicSharedMemorySize, SMEM_BYTES);

    zero_kernel<<<(out_size + 511) / 512, 512>>>(out, out_size, B);
    mp_kernel<<<(N + TM - 1) / TM, THREADS, SMEM_BYTES>>>(
        h, vi, d, ur, Wf1, bf1, Wf2, bf2, Wa, ba, Wb, bb, mapping, out, N, B);
    finalize_kernel<<<(out_size + 255) / 256, 256>>>(out, B * 128, out_size);
}